// round 16
// baseline (speedup 1.0000x reference)
#include <cuda_runtime.h>
#include <math.h>

#define B_ 256
#define S_ 128
#define E_ 256
#define H_ 512
#define G_ 2048
#define BH_ (B_*H_)
#define SB_ (S_*B_)
#define NB_ 256          // persistent grid size

// ---------------- device scratch ---------------------------------------------
__device__ float g_x   [SB_*E_];
__device__ float g_Pf  [SB_*G_];
__device__ float g_Pb  [SB_*G_];
__device__ float g_x1  [SB_*2*H_];    // layer0 h (fwd cols 0:512, bwd 512:1024)
__device__ float g_of1 [SB_*H_];
__device__ float g_ob1 [SB_*H_];
__device__ float g_enc [SB_*H_];
__device__ float g_encE[SB_*H_];
__device__ float g_cf0[BH_], g_cb0[BH_], g_cf1[BH_], g_cb1[BH_];
__device__ float g_zero[BH_];         // never written
__device__ float g_h0[2*BH_], g_h1[2*BH_];
__device__ float g_c0[BH_], g_c1[BH_];
__device__ float g_de[BH_];
__device__ float g_Pd0[G_];
__device__ float g_atts[S_*B_*S_];    // [t][b][s]
__device__ unsigned g_bar_phase;      // 0 at launch entry/exit
__device__ unsigned g_bar_count;

// ---------------- helpers ----------------------------------------------------
__device__ __forceinline__ float sigu(float x) {
    float e = __expf(-x);
    return __fdividef(1.f, 1.f + e);
}
__device__ __forceinline__ float tanhu(float x) {
    float e = __expf(2.f * x);
    return 1.f - __fdividef(2.f, 1.f + e);
}

__device__ __forceinline__ unsigned f2tf(float x) {
    unsigned r;
    asm("cvt.rna.tf32.f32 %0, %1;" : "=r"(r) : "f"(x));
    return r;
}

__device__ __forceinline__ void mma_tf32(float* c,
    unsigned a0, unsigned a1, unsigned a2, unsigned a3, unsigned b0, unsigned b1) {
    asm volatile(
        "mma.sync.aligned.m16n8k8.row.col.f32.tf32.tf32.f32 "
        "{%0,%1,%2,%3},{%4,%5,%6,%7},{%8,%9},{%0,%1,%2,%3};"
        : "+f"(c[0]), "+f"(c[1]), "+f"(c[2]), "+f"(c[3])
        : "r"(a0), "r"(a1), "r"(a2), "r"(a3), "r"(b0), "r"(b1));
}

// grid barrier: j = 1..K; barrier K resets phase to 0 (replay-safe)
__device__ __forceinline__ void gbar(int j, int K) {
    __syncthreads();
    if (threadIdx.x == 0) {
        __threadfence();
        unsigned target = (j == K) ? 0u : (unsigned)j;
        unsigned old = atomicAdd(&g_bar_count, 1u);
        if (old == NB_ - 1u) {
            atomicExch(&g_bar_count, 0u);
            __threadfence();
            *(volatile unsigned*)&g_bar_phase = target;
        } else {
            while (*(volatile unsigned*)&g_bar_phase != target) {}
        }
    }
    __syncthreads();
}

struct GArg { const float* A; const float* W; float* C; const float* bias; int N; };

// shared-memory union for the persistent kernels
struct SmemU {
    union {
        struct { unsigned A[64][36]; unsigned W[64][36]; } mm;   // 18432 B
        float Gs[64][68];                                        // 17408 B
        struct { float sv[H_]; float sde[H_]; float en[S_]; float red[128]; } at; // 5120 B
    } u;
};

// ---- tensor-core 64x64 tile: acc += A[64xH_] @ Wsel[64xH_]^T -----------------
// GATHER: smem W col c <- weight row (c&3)*H_ + h0 + (c>>2)  (gate-interleaved)
// else:   smem W col c <- weight row c (Wbase pre-offset by output col)
template<bool GATHER>
__device__ __forceinline__ void mma_tile(
    float (&acc)[4][4], SmemU& sm,
    const float* Abase, int astr, const float* Wbase, int h0,
    int wm, int wn, int g, int tig, int tid)
{
    int t8 = tig << 3;
    int r0 = (wm << 4) + g;
    for (int k0 = 0; k0 < H_; k0 += 32) {
#pragma unroll
        for (int u = 0; u < 2; u++) {
            int f = tid + (u << 8);
            int row = f >> 3, q = f & 7;
            float4 av = __ldcg((const float4*)(Abase + (size_t)row * astr + k0 + (q << 2)));
            sm.u.mm.A[row][q]      = f2tf(av.x);
            sm.u.mm.A[row][8 + q]  = f2tf(av.y);
            sm.u.mm.A[row][16 + q] = f2tf(av.z);
            sm.u.mm.A[row][24 + q] = f2tf(av.w);
            int wr = GATHER ? ((row & 3) * H_ + h0 + (row >> 2)) : row;
            float4 wv = *(const float4*)(Wbase + (size_t)wr * H_ + k0 + (q << 2));
            sm.u.mm.W[row][q]      = f2tf(wv.x);
            sm.u.mm.W[row][8 + q]  = f2tf(wv.y);
            sm.u.mm.W[row][16 + q] = f2tf(wv.z);
            sm.u.mm.W[row][24 + q] = f2tf(wv.w);
        }
        __syncthreads();
        uint4 x0 = *(const uint4*)&sm.u.mm.A[r0][t8];
        uint4 x1 = *(const uint4*)&sm.u.mm.A[r0][t8 + 4];
        uint4 y0 = *(const uint4*)&sm.u.mm.A[r0 + 8][t8];
        uint4 y1 = *(const uint4*)&sm.u.mm.A[r0 + 8][t8 + 4];
        unsigned aL[8] = {x0.x, x0.y, x0.z, x0.w, x1.x, x1.y, x1.z, x1.w};
        unsigned aH[8] = {y0.x, y0.y, y0.z, y0.w, y1.x, y1.y, y1.z, y1.w};
#pragma unroll
        for (int ni = 0; ni < 4; ni++) {
            int nr = (wn << 5) + (ni << 3) + g;
            uint4 b0v = *(const uint4*)&sm.u.mm.W[nr][t8];
            uint4 b1v = *(const uint4*)&sm.u.mm.W[nr][t8 + 4];
            unsigned bb[8] = {b0v.x, b0v.y, b0v.z, b0v.w, b1v.x, b1v.y, b1v.z, b1v.w};
#pragma unroll
            for (int j = 0; j < 4; j++)
                mma_tf32(acc[ni], aL[2*j], aH[2*j], aL[2*j+1], aH[2*j+1], bb[2*j], bb[2*j+1]);
        }
        __syncthreads();
    }
}

__device__ __forceinline__ void acc_to_Gs(float (&acc)[4][4], SmemU& sm,
                                          int wm, int wn, int g, int tig) {
    int r0 = (wm << 4) + g;
#pragma unroll
    for (int ni = 0; ni < 4; ni++) {
        int c = (wn << 5) + (ni << 3) + (tig << 1);
        sm.u.Gs[r0][c]         = acc[ni][0];
        sm.u.Gs[r0][c + 1]     = acc[ni][1];
        sm.u.Gs[r0 + 8][c]     = acc[ni][2];
        sm.u.Gs[r0 + 8][c + 1] = acc[ni][3];
    }
}

// ---------------- small kernels ----------------------------------------------
__global__ void k_embed(const int* __restrict__ inp, const float* __restrict__ emb,
                        float* __restrict__ x) {
    int i = blockIdx.x * 256 + threadIdx.x;
    int e = i & (E_ - 1);
    int r = i >> 8;
    int b = r & (B_ - 1);
    int s = r >> 8;
    x[i] = emb[(size_t)inp[b * S_ + s] * E_ + e];
}

__global__ void k_encout(const float* __restrict__ f, const float* __restrict__ b,
                         float* __restrict__ enc) {
    int i = blockIdx.x * 256 + threadIdx.x;
    int h = i & (H_ - 1);
    int r = i >> 9;
    int s = r & (S_ - 1);
    int bb = r >> 7;
    size_t src = ((size_t)s * B_ + bb) * H_ + h;
    enc[i] = f[src] + b[src];
}

__global__ void k_decinit(const float* x1, const float* of1, const float* ob1,
                          const float* cf0, const float* cb0, const float* cf1, const float* cb1,
                          float* h0, float* c0, float* h1, float* c1) {
    int i = blockIdx.x * 256 + threadIdx.x;
    int b = i >> 9, h = i & (H_ - 1);
    float hf0 = x1[((size_t)(S_ - 1) * B_ + b) * (2 * H_) + h];
    float hb0 = x1[(size_t)b * (2 * H_) + H_ + h];
    h0[i] = hf0 + hb0;
    c0[i] = cf0[i] + cb0[i];
    float hf1 = of1[((size_t)(S_ - 1) * B_ + b) * H_ + h];
    float hb1 = ob1[(size_t)b * H_ + h];
    h1[i] = hf1 + hb1;
    c1[i] = cf1[i] + cb1[i];
}

__global__ void k_vecproj(const float* __restrict__ emb, const float* __restrict__ Wi,
                          const float* __restrict__ bias, float* __restrict__ P) {
    int j = blockIdx.x * 256 + threadIdx.x;
    float s = bias[j];
    const float* w = Wi + (size_t)j * E_;
    for (int e = 0; e < E_; e++) s = fmaf(emb[e], w[e], s);
    P[j] = s;
}

// out[b][s][t] = atts[t][b][s]
__global__ void k_trans(const float* __restrict__ atts, float* __restrict__ out) {
    __shared__ float tile[32][33];
    int b = blockIdx.z, t0 = blockIdx.x * 32, s0 = blockIdx.y * 32;
    int lx = threadIdx.x & 31, ly = threadIdx.x >> 5;
    for (int i = ly; i < 32; i += 8)
        tile[i][lx] = atts[((size_t)(t0 + i) * B_ + b) * S_ + s0 + lx];
    __syncthreads();
    for (int i = ly; i < 32; i += 8)
        out[((size_t)b * S_ + s0 + i) * S_ + t0 + lx] = tile[lx][i];
}

// ---------------- bulk GEMM (tf32 tensor cores) -------------------------------
__global__ void __launch_bounds__(256, 2) k_gemm(GArg a0, GArg a1, int K) {
    GArg a = blockIdx.z ? a1 : a0;
    __shared__ unsigned As[128][36];
    __shared__ unsigned Ws[64][36];
    int bm = blockIdx.y << 7, bn = blockIdx.x << 6;
    int tid = threadIdx.x;
    int w = tid >> 5, lane = tid & 31;
    int g = lane >> 2, tig = lane & 3;
    int warpM = (w >> 1) << 5;
    int warpN = (w & 1) << 5;
    int t8 = tig << 3;

    float acc[2][4][4];
#pragma unroll
    for (int mi = 0; mi < 2; mi++)
#pragma unroll
        for (int ni = 0; ni < 4; ni++)
#pragma unroll
            for (int q = 0; q < 4; q++) acc[mi][ni][q] = 0.f;

    const float* Ab = a.A + (size_t)bm * K;
    const float* Wb = a.W + (size_t)bn * K;

    int arow[4], aq[4], wrow[2], wq[2];
#pragma unroll
    for (int u = 0; u < 4; u++) { int f = tid + (u << 8); arow[u] = f >> 3; aq[u] = f & 7; }
#pragma unroll
    for (int u = 0; u < 2; u++) { int f = tid + (u << 8); wrow[u] = f >> 3; wq[u] = f & 7; }

    float4 ra[4], rw[2];
#pragma unroll
    for (int u = 0; u < 4; u++)
        ra[u] = *(const float4*)(Ab + (size_t)arow[u] * K + (aq[u] << 2));
#pragma unroll
    for (int u = 0; u < 2; u++)
        rw[u] = *(const float4*)(Wb + (size_t)wrow[u] * K + (wq[u] << 2));

    for (int k0 = 0; k0 < K; k0 += 32) {
#pragma unroll
        for (int u = 0; u < 4; u++) {
            As[arow[u]][aq[u]]      = f2tf(ra[u].x);
            As[arow[u]][8 + aq[u]]  = f2tf(ra[u].y);
            As[arow[u]][16 + aq[u]] = f2tf(ra[u].z);
            As[arow[u]][24 + aq[u]] = f2tf(ra[u].w);
        }
#pragma unroll
        for (int u = 0; u < 2; u++) {
            Ws[wrow[u]][wq[u]]      = f2tf(rw[u].x);
            Ws[wrow[u]][8 + wq[u]]  = f2tf(rw[u].y);
            Ws[wrow[u]][16 + wq[u]] = f2tf(rw[u].z);
            Ws[wrow[u]][24 + wq[u]] = f2tf(rw[u].w);
        }
        __syncthreads();

        if (k0 + 32 < K) {
            int kn = k0 + 32;
#pragma unroll
            for (int u = 0; u < 4; u++)
                ra[u] = *(const float4*)(Ab + (size_t)arow[u] * K + kn + (aq[u] << 2));
#pragma unroll
            for (int u = 0; u < 2; u++)
                rw[u] = *(const float4*)(Wb + (size_t)wrow[u] * K + kn + (wq[u] << 2));
        }

        unsigned aL[2][8], aH[2][8];
#pragma unroll
        for (int mi = 0; mi < 2; mi++) {
            int r0 = warpM + (mi << 4) + g;
            const uint4* pL = (const uint4*)&As[r0][t8];
            const uint4* pH = (const uint4*)&As[r0 + 8][t8];
            uint4 x0 = pL[0], x1v = pL[1], y0 = pH[0], y1 = pH[1];
            aL[mi][0] = x0.x; aL[mi][1] = x0.y; aL[mi][2] = x0.z; aL[mi][3] = x0.w;
            aL[mi][4] = x1v.x; aL[mi][5] = x1v.y; aL[mi][6] = x1v.z; aL[mi][7] = x1v.w;
            aH[mi][0] = y0.x; aH[mi][1] = y0.y; aH[mi][2] = y0.z; aH[mi][3] = y0.w;
            aH[mi][4] = y1.x; aH[mi][5] = y1.y; aH[mi][6] = y1.z; aH[mi][7] = y1.w;
        }
#pragma unroll
        for (int ni = 0; ni < 4; ni++) {
            int nr = warpN + (ni << 3) + g;
            const uint4* pB = (const uint4*)&Ws[nr][t8];
            uint4 b0 = pB[0], b1 = pB[1];
            unsigned bb[8] = {b0.x, b0.y, b0.z, b0.w, b1.x, b1.y, b1.z, b1.w};
#pragma unroll
            for (int mi = 0; mi < 2; mi++) {
#pragma unroll
                for (int j = 0; j < 4; j++) {
                    mma_tf32(acc[mi][ni],
                             aL[mi][2 * j], aH[mi][2 * j],
                             aL[mi][2 * j + 1], aH[mi][2 * j + 1],
                             bb[2 * j], bb[2 * j + 1]);
                }
            }
        }
        __syncthreads();
    }

#pragma unroll
    for (int mi = 0; mi < 2; mi++) {
        int r0 = bm + warpM + (mi << 4) + g;
#pragma unroll
        for (int ni = 0; ni < 4; ni++) {
            int c = bn + warpN + (ni << 3) + (tig << 1);
            float bz0 = a.bias[c], bz1 = a.bias[c + 1];
            float* p0 = a.C + (size_t)r0 * a.N + c;
            float* p1 = a.C + (size_t)(r0 + 8) * a.N + c;
            p0[0] = acc[mi][ni][0] + bz0;
            p0[1] = acc[mi][ni][1] + bz1;
            p1[0] = acc[mi][ni][2] + bz0;
            p1[1] = acc[mi][ni][3] + bz1;
        }
    }
}

// ---------------- persistent bi-LSTM scan (tensor cores) ----------------------
// 256 blocks = 2 dirs x (4 m-tiles x 32 n-tiles); tile [64 batch x (16h x 4g)].
__global__ void __launch_bounds__(256, 2) k_enc(
    const float* Pf, const float* Pb, const float* Whf, const float* Whb,
    float* oF, float* oB, int ostr, int offF, int offB,
    float* cF, float* cB, const float* zero)
{
    __shared__ SmemU sm;
    int bid = blockIdx.x;
    int dir = bid >> 7, tt = bid & 127;
    int bm = (tt >> 5) << 6, h0 = (tt & 31) << 4;
    const float* W = dir ? Whb : Whf;
    const float* P = dir ? Pb : Pf;
    float* outp = dir ? oB : oF;
    int off = dir ? offB : offF;
    int tid = threadIdx.x;
    int w = tid >> 5, lane = tid & 31, g = lane >> 2, tig = lane & 3;
    int wm = w >> 1, wn = w & 1;
    int tx = tid & 15, ty = tid >> 4;
    int hh = h0 + tx;
    float creg[4] = {0.f, 0.f, 0.f, 0.f};

    for (int t = 0; t < S_; t++) {
        int ti = dir ? (S_ - 1 - t) : t;
        const float* Abase;
        int astr;
        if (t == 0) { Abase = zero + (size_t)bm * H_; astr = H_; }
        else {
            int tp = dir ? (ti + 1) : (ti - 1);
            Abase = outp + (size_t)tp * B_ * ostr + off + (size_t)bm * ostr;
            astr = ostr;
        }
        float acc[4][4];
#pragma unroll
        for (int ni = 0; ni < 4; ni++)
#pragma unroll
            for (int q = 0; q < 4; q++) acc[ni][q] = 0.f;

        mma_tile<true>(acc, sm, Abase, astr, W, h0, wm, wn, g, tig, tid);
        acc_to_Gs(acc, sm, wm, wn, g, tig);
        __syncthreads();

#pragma unroll
        for (int i = 0; i < 4; i++) {
            int b = bm + (ty << 2) + i;
            float4 gq = *(const float4*)&sm.u.Gs[(ty << 2) + i][tx << 2];
            const float* Pr = P + ((size_t)ti * B_ + b) * G_;
            float gi = gq.x + Pr[hh];
            float gf = gq.y + Pr[H_ + hh];
            float gg = gq.z + Pr[2 * H_ + hh];
            float go = gq.w + Pr[3 * H_ + hh];
            float cn = sigu(gf) * creg[i] + sigu(gi) * tanhu(gg);
            creg[i] = cn;
            outp[(size_t)ti * B_ * ostr + (size_t)b * ostr + off + hh] = sigu(go) * tanhu(cn);
        }
        gbar(t + 1, S_);
    }
    float* cd = dir ? cB : cF;
#pragma unroll
    for (int i = 0; i < 4; i++) cd[(size_t)(bm + (ty << 2) + i) * H_ + hh] = creg[i];
}

// ---------------- persistent decoder -----------------------------------------
__device__ __forceinline__ void attn_batch(
    int b, int tout, const float* de, const float* encE, const float* v,
    float* atts, float* sv, float* sde, float* en, float* red)
{
    int tid = threadIdx.x;
    for (int i = tid; i < H_; i += 256) {
        sv[i] = v[i];
        sde[i] = __ldcg(de + (size_t)b * H_ + i);
    }
    __syncthreads();
    int warp = tid >> 5, lane = tid & 31;
    for (int s = warp; s < S_; s += 8) {
        const float* row = encE + ((size_t)b * S_ + s) * H_;
        float acc = 0.f;
        for (int h = lane; h < H_; h += 32)
            acc += tanhu(__ldg(row + h) + sde[h]) * sv[h];
#pragma unroll
        for (int o = 16; o > 0; o >>= 1) acc += __shfl_xor_sync(0xffffffffu, acc, o);
        if (lane == 0) en[s] = acc;
    }
    __syncthreads();
    if (tid < 128) red[tid] = en[tid];
    __syncthreads();
    for (int st = 64; st > 0; st >>= 1) {
        if (tid < st) red[tid] = fmaxf(red[tid], red[tid + st]);
        __syncthreads();
    }
    float mx = red[0];
    __syncthreads();
    float ex = 0.f;
    if (tid < 128) { ex = __expf(en[tid] - mx); red[tid] = ex; }
    __syncthreads();
    for (int st = 64; st > 0; st >>= 1) {
        if (tid < st) red[tid] += red[tid + st];
        __syncthreads();
    }
    float inv = __fdividef(1.f, red[0]);
    if (tid < 128) atts[((size_t)tout * B_ + b) * S_ + tid] = ex * inv;
    __syncthreads();
}

__global__ void __launch_bounds__(256, 2) k_dec(
    const float* d0Wh, const float* d1Wi, const float* d1Wh,
    const float* w2, const float* b2, const float* Pd0, const float* d1b,
    float* h0p, float* h1p, const float* c0i, const float* c1i,
    const float* encE, const float* v, float* de, float* atts)
{
    const int KD = 3 * S_ + 1;
    __shared__ SmemU sm;
    int bid = blockIdx.x, tid = threadIdx.x;
    int w = tid >> 5, lane = tid & 31, g = lane >> 2, tig = lane & 3;
    int wm = w >> 1, wn = w & 1;
    int tx = tid & 15, ty = tid >> 4;

    // cell0/cell1 tiles (blocks 0-127): [64b x (16h x 4g)]
    int bmc = ((bid & 127) >> 5) << 6, h0c = (bid & 31) << 4;
    int hhc = h0c + tx;
    float c0reg[4], c1reg[4];
    if (bid < 128) {
#pragma unroll
        for (int i = 0; i < 4; i++) {
            c0reg[i] = c0i[(size_t)(bmc + (ty << 2) + i) * H_ + hhc];
            c1reg[i] = c1i[(size_t)(bmc + (ty << 2) + i) * H_ + hhc];
        }
    }

    int bars = 0;
    for (int t = 0; t < S_; t++) {
        const float* h0r = h0p + (size_t)(t & 1) * BH_;
        float* h0w = h0p + (size_t)((t & 1) ^ 1) * BH_;
        const float* h1r = h1p + (size_t)(t & 1) * BH_;
        float* h1w = h1p + (size_t)((t & 1) ^ 1) * BH_;

        // ---- ph1: cell0 (0-127) || attention batch A for t-1 (128-255)
        if (bid < 128) {
            float acc[4][4];
#pragma unroll
            for (int ni = 0; ni < 4; ni++)
#pragma unroll
                for (int q = 0; q < 4; q++) acc[ni][q] = 0.f;
            mma_tile<true>(acc, sm, h0r + (size_t)bmc * H_, H_, d0Wh, h0c, wm, wn, g, tig, tid);
            acc_to_Gs(acc, sm, wm, wn, g, tig);
            __syncthreads();
            float pi = Pd0[hhc], pf = Pd0[H_ + hhc], pg = Pd0[2 * H_ + hhc], po = Pd0[3 * H_ + hhc];
#pragma unroll
            for (int i = 0; i < 4; i++) {
                int b = bmc + (ty << 2) + i;
                float4 gq = *(const float4*)&sm.u.Gs[(ty << 2) + i][tx << 2];
                float cn = sigu(gq.y + pf) * c0reg[i] + sigu(gq.x + pi) * tanhu(gq.z + pg);
                c0reg[i] = cn;
                h0w[(size_t)b * H_ + hhc] = sigu(gq.w + po) * tanhu(cn);
            }
        } else if (t > 0) {
            attn_batch((bid - 128) * 2, t - 1, de, encE, v, atts,
                       sm.u.at.sv, sm.u.at.sde, sm.u.at.en, sm.u.at.red);
        }
        gbar(++bars, KD);

        // ---- ph2: cell1 (0-127, K=1024 over two halves) || attention batch B
        if (bid < 128) {
            float acc[4][4];
#pragma unroll
            for (int ni = 0; ni < 4; ni++)
#pragma unroll
                for (int q = 0; q < 4; q++) acc[ni][q] = 0.f;
            mma_tile<true>(acc, sm, h0w + (size_t)bmc * H_, H_, d1Wi, h0c, wm, wn, g, tig, tid);
            mma_tile<true>(acc, sm, h1r + (size_t)bmc * H_, H_, d1Wh, h0c, wm, wn, g, tig, tid);
            acc_to_Gs(acc, sm, wm, wn, g, tig);
            __syncthreads();
            float pi = d1b[hhc], pf = d1b[H_ + hhc], pg = d1b[2 * H_ + hhc], po = d1b[3 * H_ + hhc];
#pragma unroll
            for (int i = 0; i < 4; i++) {
                int b = bmc + (ty << 2) + i;
                float4 gq = *(const float4*)&sm.u.Gs[(ty << 2) + i][tx << 2];
                float cn = sigu(gq.y + pf) * c1reg[i] + sigu(gq.x + pi) * tanhu(gq.z + pg);
                c1reg[i] = cn;
                h1w[(size_t)b * H_ + hhc] = sigu(gq.w + po) * tanhu(cn);
            }
        } else if (t > 0) {
            attn_batch((bid - 128) * 2 + 1, t - 1, de, encE, v, atts,
                       sm.u.at.sv, sm.u.at.sde, sm.u.at.en, sm.u.at.red);
        }
        gbar(++bars, KD);

        // ---- ph3: de = h1w @ w2^T + b2 (blocks 0-31, 64x64 plain tiles)
        if (bid < 32) {
            int bm = (bid >> 3) << 6, bn = (bid & 7) << 6;
            float acc[4][4];
#pragma unroll
            for (int ni = 0; ni < 4; ni++)
#pragma unroll
                for (int q = 0; q < 4; q++) acc[ni][q] = 0.f;
            mma_tile<false>(acc, sm, h1w + (size_t)bm * H_, H_, w2 + (size_t)bn * H_, 0,
                            wm, wn, g, tig, tid);
            int r0 = bm + (wm << 4) + g;
#pragma unroll
            for (int ni = 0; ni < 4; ni++) {
                int c = bn + (wn << 5) + (ni << 3) + (tig << 1);
                float bz0 = b2[c], bz1 = b2[c + 1];
                de[(size_t)r0 * H_ + c]           = acc[ni][0] + bz0;
                de[(size_t)r0 * H_ + c + 1]       = acc[ni][1] + bz1;
                de[(size_t)(r0 + 8) * H_ + c]     = acc[ni][2] + bz0;
                de[(size_t)(r0 + 8) * H_ + c + 1] = acc[ni][3] + bz1;
            }
        }
        gbar(++bars, KD);
    }
    // tail: attention for t = S_-1, one batch per block
    attn_batch(bid, S_ - 1, de, encE, v, atts,
               sm.u.at.sv, sm.u.at.sde, sm.u.at.en, sm.u.at.red);
    gbar(++bars, KD);
}

// ---------------- host driver ------------------------------------------------
extern "C" void kernel_launch(void* const* d_in, const int* in_sizes, int n_in,
                              void* d_out, int out_size) {
    const int*   inputs = (const int*)d_in[0];
    const float* emb    = (const float*)d_in[1];
    const float* e0f_Wi = (const float*)d_in[2];
    const float* e0f_Wh = (const float*)d_in[3];
    const float* e0f_b  = (const float*)d_in[4];
    const float* e0b_Wi = (const float*)d_in[5];
    const float* e0b_Wh = (const float*)d_in[6];
    const float* e0b_b  = (const float*)d_in[7];
    const float* e1f_Wi = (const float*)d_in[8];
    const float* e1f_Wh = (const float*)d_in[9];
    const float* e1f_b  = (const float*)d_in[10];
    const float* e1b_Wi = (const float*)d_in[11];
    const float* e1b_Wh = (const float*)d_in[12];
    const float* e1b_b  = (const float*)d_in[13];
    const float* d0_Wi  = (const float*)d_in[14];
    const float* d0_Wh  = (const float*)d_in[15];
    const float* d0_b   = (const float*)d_in[16];
    const float* d1_Wi  = (const float*)d_in[17];
    const float* d1_Wh  = (const float*)d_in[18];
    const float* d1_b   = (const float*)d_in[19];
    const float* w1     = (const float*)d_in[20];
    const float* b1     = (const float*)d_in[21];
    const float* w2     = (const float*)d_in[22];
    const float* b2     = (const float*)d_in[23];
    const float* v      = (const float*)d_in[24];
    float* out = (float*)d_out;

    float *x, *Pf, *Pb, *x1, *of1, *ob1, *enc, *encE;
    float *cf0, *cb0, *cf1, *cb1, *zero, *h0, *h1, *c0, *c1, *de, *Pd0, *atts;
    cudaGetSymbolAddress((void**)&x, g_x);
    cudaGetSymbolAddress((void**)&Pf, g_Pf);
    cudaGetSymbolAddress((void**)&Pb, g_Pb);
    cudaGetSymbolAddress((void**)&x1, g_x1);
    cudaGetSymbolAddress((void**)&of1, g_of1);
    cudaGetSymbolAddress((void**)&ob1, g_ob1);
    cudaGetSymbolAddress((void**)&enc, g_enc);
    cudaGetSymbolAddress((void**)&encE, g_encE);
    cudaGetSymbolAddress((void**)&cf0, g_cf0);
    cudaGetSymbolAddress((void**)&cb0, g_cb0);
    cudaGetSymbolAddress((void**)&cf1, g_cf1);
    cudaGetSymbolAddress((void**)&cb1, g_cb1);
    cudaGetSymbolAddress((void**)&zero, g_zero);
    cudaGetSymbolAddress((void**)&h0, g_h0);
    cudaGetSymbolAddress((void**)&h1, g_h1);
    cudaGetSymbolAddress((void**)&c0, g_c0);
    cudaGetSymbolAddress((void**)&c1, g_c1);
    cudaGetSymbolAddress((void**)&de, g_de);
    cudaGetSymbolAddress((void**)&Pd0, g_Pd0);
    cudaGetSymbolAddress((void**)&atts, g_atts);

    // 1) embedding
    k_embed<<<SB_ * E_ / 256, 256>>>(inputs, emb, x);

    // 2) layer0 input projections + scan (h written into x1 halves)
    {
        GArg f{x, e0f_Wi, Pf, e0f_b, G_};
        GArg b{x, e0b_Wi, Pb, e0b_b, G_};
        k_gemm<<<dim3(G_ / 64, SB_ / 128, 2), 256>>>(f, b, E_);
    }
    k_enc<<<NB_, 256>>>(Pf, Pb, e0f_Wh, e0b_Wh, x1, x1, 2 * H_, 0, H_, cf0, cb0, zero);

    // 3) layer1 input projections + scan
    {
        GArg f{x1, e1f_Wi, Pf, e1f_b, G_};
        GArg b{x1, e1b_Wi, Pb, e1b_b, G_};
        k_gemm<<<dim3(G_ / 64, SB_ / 128, 2), 256>>>(f, b, 2 * H_);
    }
    k_enc<<<NB_, 256>>>(Pf, Pb, e1f_Wh, e1b_Wh, of1, ob1, H_, 0, 0, cf1, cb1, zero);

    // 4) encoder out + hoisted attention energy
    k_encout<<<SB_ * H_ / 256, 256>>>(of1, ob1, enc);
    {
        GArg a{enc, w1, encE, b1, H_};
        k_gemm<<<dim3(H_ / 64, SB_ / 128, 1), 256>>>(a, a, H_);
    }

    // 5) decoder init + constant input projection
    k_decinit<<<BH_ / 256, 256>>>(x1, of1, ob1, cf0, cb0, cf1, cb1, h0, c0, h1, c1);
    k_vecproj<<<G_ / 256, 256>>>(emb, d0_Wi, d0_b, Pd0);

    // 6) decoder (persistent)
    k_dec<<<NB_, 256>>>(d0_Wh, d1_Wi, d1_Wh, w2, b2, Pd0, d1_b,
                        h0, h1, c0, c1, encE, v, de, atts);

    // 7) transpose atts[t][b][s] -> out[b][s][t]
    k_trans<<<dim3(S_ / 32, S_ / 32, B_), 256>>>(atts, out);
}

// round 17
// speedup vs baseline: 1.0798x; 1.0798x over previous
#include <cuda_runtime.h>
#include <math.h>

#define B_ 256
#define S_ 128
#define E_ 256
#define H_ 512
#define G_ 2048
#define BH_ (B_*H_)
#define SB_ (S_*B_)
#define NB_ 256          // persistent grid size

// ---------------- device scratch ---------------------------------------------
__device__ float g_x   [SB_*E_];
__device__ float g_Pf  [SB_*G_];
__device__ float g_Pb  [SB_*G_];
__device__ float g_x1  [SB_*2*H_];    // layer0 h (fwd cols 0:512, bwd 512:1024)
__device__ float g_of1 [SB_*H_];
__device__ float g_ob1 [SB_*H_];
__device__ float g_enc [SB_*H_];
__device__ float g_encE[SB_*H_];
__device__ float g_cf0[BH_], g_cb0[BH_], g_cf1[BH_], g_cb1[BH_];
__device__ float g_zero[BH_];         // never written
__device__ float g_h0[2*BH_], g_h1[2*BH_];
__device__ float g_c0[BH_], g_c1[BH_];
__device__ float g_de[BH_];
__device__ float g_Pd0[G_];
__device__ float g_atts[S_*B_*S_];    // [t][b][s]
__device__ unsigned g_bar_phase;      // 0 at launch entry/exit
__device__ unsigned g_flags[NB_*8];   // per-block arrival flags, 32B apart; 0 at entry/exit

// ---------------- helpers ----------------------------------------------------
__device__ __forceinline__ float sigu(float x) {
    float e = __expf(-x);
    return __fdividef(1.f, 1.f + e);
}
__device__ __forceinline__ float tanhu(float x) {
    float e = __expf(2.f * x);
    return 1.f - __fdividef(2.f, 1.f + e);
}

__device__ __forceinline__ unsigned f2tf(float x) {
    unsigned r;
    asm("cvt.rna.tf32.f32 %0, %1;" : "=r"(r) : "f"(x));
    return r;
}

__device__ __forceinline__ void mma_tf32(float* c,
    unsigned a0, unsigned a1, unsigned a2, unsigned a3, unsigned b0, unsigned b1) {
    asm volatile(
        "mma.sync.aligned.m16n8k8.row.col.f32.tf32.tf32.f32 "
        "{%0,%1,%2,%3},{%4,%5,%6,%7},{%8,%9},{%0,%1,%2,%3};"
        : "+f"(c[0]), "+f"(c[1]), "+f"(c[2]), "+f"(c[3])
        : "r"(a0), "r"(a1), "r"(a2), "r"(a3), "r"(b0), "r"(b1));
}

// flag-array grid barrier: j = 1..K; barrier K resets phase+flags to 0 (replay-safe).
// Arrivals are parallel STGs to distinct 32B sectors (no atomic contention);
// block 0 aggregates with 256 polling threads and releases via one phase write.
__device__ __forceinline__ void gbar(int j, int K) {
    unsigned target = (j == K) ? 0u : (unsigned)j;
    __syncthreads();
    if (blockIdx.x == 0) {
        int tid = threadIdx.x;
        if (tid > 0) {
            while (*(volatile unsigned*)&g_flags[tid * 8] != (unsigned)j) {}
        }
        __syncthreads();
        if (j == K) g_flags[tid * 8] = 0u;
        if (tid == 0) {
            __threadfence();
            *(volatile unsigned*)&g_bar_phase = target;
        }
    } else {
        if (threadIdx.x == 0) {
            __threadfence();
            *(volatile unsigned*)&g_flags[blockIdx.x * 8] = (unsigned)j;
            while (*(volatile unsigned*)&g_bar_phase != target) {}
            __threadfence();
        }
        __syncthreads();
    }
}

struct GArg { const float* A; const float* W; float* C; const float* bias; int N; };

// shared-memory union for the persistent kernels
struct SmemU {
    union {
        struct { unsigned A[64][36]; unsigned W[64][36]; } mm;   // 18432 B
        float Gs[64][68];                                        // 17408 B
        struct { float sv[H_]; float sde[H_]; float en[S_]; float red[128]; } at; // 5120 B
    } u;
};

// ---- tensor-core 64x64 tile: acc += A[64xH_] @ Wsel[64xH_]^T -----------------
// GATHER: smem W col c <- weight row (c&3)*H_ + h0 + (c>>2)  (gate-interleaved)
// else:   smem W col c <- weight row c (Wbase pre-offset by output col)
// Register-prefetch pipeline: next chunk's global loads overlap current MMAs.
template<bool GATHER>
__device__ __forceinline__ void mma_tile(
    float (&acc)[4][4], SmemU& sm,
    const float* Abase, int astr, const float* Wbase, int h0,
    int wm, int wn, int g, int tig, int tid)
{
    int t8 = tig << 3;
    int r0 = (wm << 4) + g;
    int row0 = tid >> 3, q0 = tid & 7;
    int row1 = row0 + 32;
    int wr0 = GATHER ? ((row0 & 3) * H_ + h0 + (row0 >> 2)) : row0;
    int wr1 = GATHER ? ((row1 & 3) * H_ + h0 + (row1 >> 2)) : row1;
    const float* Ap0 = Abase + (size_t)row0 * astr + (q0 << 2);
    const float* Ap1 = Abase + (size_t)row1 * astr + (q0 << 2);
    const float* Wp0 = Wbase + (size_t)wr0 * H_ + (q0 << 2);
    const float* Wp1 = Wbase + (size_t)wr1 * H_ + (q0 << 2);

    float4 ra0 = __ldcg((const float4*)Ap0);
    float4 ra1 = __ldcg((const float4*)Ap1);
    float4 rw0 = *(const float4*)Wp0;
    float4 rw1 = *(const float4*)Wp1;

    for (int k0 = 0; k0 < H_; k0 += 32) {
        sm.u.mm.A[row0][q0]      = f2tf(ra0.x);
        sm.u.mm.A[row0][8 + q0]  = f2tf(ra0.y);
        sm.u.mm.A[row0][16 + q0] = f2tf(ra0.z);
        sm.u.mm.A[row0][24 + q0] = f2tf(ra0.w);
        sm.u.mm.A[row1][q0]      = f2tf(ra1.x);
        sm.u.mm.A[row1][8 + q0]  = f2tf(ra1.y);
        sm.u.mm.A[row1][16 + q0] = f2tf(ra1.z);
        sm.u.mm.A[row1][24 + q0] = f2tf(ra1.w);
        sm.u.mm.W[row0][q0]      = f2tf(rw0.x);
        sm.u.mm.W[row0][8 + q0]  = f2tf(rw0.y);
        sm.u.mm.W[row0][16 + q0] = f2tf(rw0.z);
        sm.u.mm.W[row0][24 + q0] = f2tf(rw0.w);
        sm.u.mm.W[row1][q0]      = f2tf(rw1.x);
        sm.u.mm.W[row1][8 + q0]  = f2tf(rw1.y);
        sm.u.mm.W[row1][16 + q0] = f2tf(rw1.z);
        sm.u.mm.W[row1][24 + q0] = f2tf(rw1.w);
        __syncthreads();

        if (k0 + 32 < H_) {
            ra0 = __ldcg((const float4*)(Ap0 + k0 + 32));
            ra1 = __ldcg((const float4*)(Ap1 + k0 + 32));
            rw0 = *(const float4*)(Wp0 + k0 + 32);
            rw1 = *(const float4*)(Wp1 + k0 + 32);
        }

        uint4 x0 = *(const uint4*)&sm.u.mm.A[r0][t8];
        uint4 x1 = *(const uint4*)&sm.u.mm.A[r0][t8 + 4];
        uint4 y0 = *(const uint4*)&sm.u.mm.A[r0 + 8][t8];
        uint4 y1 = *(const uint4*)&sm.u.mm.A[r0 + 8][t8 + 4];
        unsigned aL[8] = {x0.x, x0.y, x0.z, x0.w, x1.x, x1.y, x1.z, x1.w};
        unsigned aH[8] = {y0.x, y0.y, y0.z, y0.w, y1.x, y1.y, y1.z, y1.w};
#pragma unroll
        for (int ni = 0; ni < 4; ni++) {
            int nr = (wn << 5) + (ni << 3) + g;
            uint4 b0v = *(const uint4*)&sm.u.mm.W[nr][t8];
            uint4 b1v = *(const uint4*)&sm.u.mm.W[nr][t8 + 4];
            unsigned bb[8] = {b0v.x, b0v.y, b0v.z, b0v.w, b1v.x, b1v.y, b1v.z, b1v.w};
#pragma unroll
            for (int j = 0; j < 4; j++)
                mma_tf32(acc[ni], aL[2*j], aH[2*j], aL[2*j+1], aH[2*j+1], bb[2*j], bb[2*j+1]);
        }
        __syncthreads();
    }
}

__device__ __forceinline__ void acc_to_Gs(float (&acc)[4][4], SmemU& sm,
                                          int wm, int wn, int g, int tig) {
    int r0 = (wm << 4) + g;
#pragma unroll
    for (int ni = 0; ni < 4; ni++) {
        int c = (wn << 5) + (ni << 3) + (tig << 1);
        sm.u.Gs[r0][c]         = acc[ni][0];
        sm.u.Gs[r0][c + 1]     = acc[ni][1];
        sm.u.Gs[r0 + 8][c]     = acc[ni][2];
        sm.u.Gs[r0 + 8][c + 1] = acc[ni][3];
    }
}

// ---------------- small kernels ----------------------------------------------
__global__ void k_embed(const int* __restrict__ inp, const float* __restrict__ emb,
                        float* __restrict__ x) {
    int i = blockIdx.x * 256 + threadIdx.x;
    int e = i & (E_ - 1);
    int r = i >> 8;
    int b = r & (B_ - 1);
    int s = r >> 8;
    x[i] = emb[(size_t)inp[b * S_ + s] * E_ + e];
}

__global__ void k_encout(const float* __restrict__ f, const float* __restrict__ b,
                         float* __restrict__ enc) {
    int i = blockIdx.x * 256 + threadIdx.x;
    int h = i & (H_ - 1);
    int r = i >> 9;
    int s = r & (S_ - 1);
    int bb = r >> 7;
    size_t src = ((size_t)s * B_ + bb) * H_ + h;
    enc[i] = f[src] + b[src];
}

__global__ void k_decinit(const float* x1, const float* of1, const float* ob1,
                          const float* cf0, const float* cb0, const float* cf1, const float* cb1,
                          float* h0, float* c0, float* h1, float* c1) {
    int i = blockIdx.x * 256 + threadIdx.x;
    int b = i >> 9, h = i & (H_ - 1);
    float hf0 = x1[((size_t)(S_ - 1) * B_ + b) * (2 * H_) + h];
    float hb0 = x1[(size_t)b * (2 * H_) + H_ + h];
    h0[i] = hf0 + hb0;
    c0[i] = cf0[i] + cb0[i];
    float hf1 = of1[((size_t)(S_ - 1) * B_ + b) * H_ + h];
    float hb1 = ob1[(size_t)b * H_ + h];
    h1[i] = hf1 + hb1;
    c1[i] = cf1[i] + cb1[i];
}

__global__ void k_vecproj(const float* __restrict__ emb, const float* __restrict__ Wi,
                          const float* __restrict__ bias, float* __restrict__ P) {
    int j = blockIdx.x * 256 + threadIdx.x;
    float s = bias[j];
    const float* w = Wi + (size_t)j * E_;
    for (int e = 0; e < E_; e++) s = fmaf(emb[e], w[e], s);
    P[j] = s;
}

// out[b][s][t] = atts[t][b][s]
__global__ void k_trans(const float* __restrict__ atts, float* __restrict__ out) {
    __shared__ float tile[32][33];
    int b = blockIdx.z, t0 = blockIdx.x * 32, s0 = blockIdx.y * 32;
    int lx = threadIdx.x & 31, ly = threadIdx.x >> 5;
    for (int i = ly; i < 32; i += 8)
        tile[i][lx] = atts[((size_t)(t0 + i) * B_ + b) * S_ + s0 + lx];
    __syncthreads();
    for (int i = ly; i < 32; i += 8)
        out[((size_t)b * S_ + s0 + i) * S_ + t0 + lx] = tile[lx][i];
}

// ---------------- bulk GEMM (tf32 tensor cores) -------------------------------
__global__ void __launch_bounds__(256, 2) k_gemm(GArg a0, GArg a1, int K) {
    GArg a = blockIdx.z ? a1 : a0;
    __shared__ unsigned As[128][36];
    __shared__ unsigned Ws[64][36];
    int bm = blockIdx.y << 7, bn = blockIdx.x << 6;
    int tid = threadIdx.x;
    int w = tid >> 5, lane = tid & 31;
    int g = lane >> 2, tig = lane & 3;
    int warpM = (w >> 1) << 5;
    int warpN = (w & 1) << 5;
    int t8 = tig << 3;

    float acc[2][4][4];
#pragma unroll
    for (int mi = 0; mi < 2; mi++)
#pragma unroll
        for (int ni = 0; ni < 4; ni++)
#pragma unroll
            for (int q = 0; q < 4; q++) acc[mi][ni][q] = 0.f;

    const float* Ab = a.A + (size_t)bm * K;
    const float* Wb = a.W + (size_t)bn * K;

    int arow[4], aq[4], wrow[2], wq[2];
#pragma unroll
    for (int u = 0; u < 4; u++) { int f = tid + (u << 8); arow[u] = f >> 3; aq[u] = f & 7; }
#pragma unroll
    for (int u = 0; u < 2; u++) { int f = tid + (u << 8); wrow[u] = f >> 3; wq[u] = f & 7; }

    float4 ra[4], rw[2];
#pragma unroll
    for (int u = 0; u < 4; u++)
        ra[u] = *(const float4*)(Ab + (size_t)arow[u] * K + (aq[u] << 2));
#pragma unroll
    for (int u = 0; u < 2; u++)
        rw[u] = *(const float4*)(Wb + (size_t)wrow[u] * K + (wq[u] << 2));

    for (int k0 = 0; k0 < K; k0 += 32) {
#pragma unroll
        for (int u = 0; u < 4; u++) {
            As[arow[u]][aq[u]]      = f2tf(ra[u].x);
            As[arow[u]][8 + aq[u]]  = f2tf(ra[u].y);
            As[arow[u]][16 + aq[u]] = f2tf(ra[u].z);
            As[arow[u]][24 + aq[u]] = f2tf(ra[u].w);
        }
#pragma unroll
        for (int u = 0; u < 2; u++) {
            Ws[wrow[u]][wq[u]]      = f2tf(rw[u].x);
            Ws[wrow[u]][8 + wq[u]]  = f2tf(rw[u].y);
            Ws[wrow[u]][16 + wq[u]] = f2tf(rw[u].z);
            Ws[wrow[u]][24 + wq[u]] = f2tf(rw[u].w);
        }
        __syncthreads();

        if (k0 + 32 < K) {
            int kn = k0 + 32;
#pragma unroll
            for (int u = 0; u < 4; u++)
                ra[u] = *(const float4*)(Ab + (size_t)arow[u] * K + kn + (aq[u] << 2));
#pragma unroll
            for (int u = 0; u < 2; u++)
                rw[u] = *(const float4*)(Wb + (size_t)wrow[u] * K + kn + (wq[u] << 2));
        }

        unsigned aL[2][8], aH[2][8];
#pragma unroll
        for (int mi = 0; mi < 2; mi++) {
            int r0 = warpM + (mi << 4) + g;
            const uint4* pL = (const uint4*)&As[r0][t8];
            const uint4* pH = (const uint4*)&As[r0 + 8][t8];
            uint4 x0 = pL[0], x1v = pL[1], y0 = pH[0], y1 = pH[1];
            aL[mi][0] = x0.x; aL[mi][1] = x0.y; aL[mi][2] = x0.z; aL[mi][3] = x0.w;
            aL[mi][4] = x1v.x; aL[mi][5] = x1v.y; aL[mi][6] = x1v.z; aL[mi][7] = x1v.w;
            aH[mi][0] = y0.x; aH[mi][1] = y0.y; aH[mi][2] = y0.z; aH[mi][3] = y0.w;
            aH[mi][4] = y1.x; aH[mi][5] = y1.y; aH[mi][6] = y1.z; aH[mi][7] = y1.w;
        }
#pragma unroll
        for (int ni = 0; ni < 4; ni++) {
            int nr = warpN + (ni << 3) + g;
            const uint4* pB = (const uint4*)&Ws[nr][t8];
            uint4 b0 = pB[0], b1 = pB[1];
            unsigned bb[8] = {b0.x, b0.y, b0.z, b0.w, b1.x, b1.y, b1.z, b1.w};
#pragma unroll
            for (int mi = 0; mi < 2; mi++) {
#pragma unroll
                for (int j = 0; j < 4; j++) {
                    mma_tf32(acc[mi][ni],
                             aL[mi][2 * j], aH[mi][2 * j],
                             aL[mi][2 * j + 1], aH[mi][2 * j + 1],
                             bb[2 * j], bb[2 * j + 1]);
                }
            }
        }
        __syncthreads();
    }

#pragma unroll
    for (int mi = 0; mi < 2; mi++) {
        int r0 = bm + warpM + (mi << 4) + g;
#pragma unroll
        for (int ni = 0; ni < 4; ni++) {
            int c = bn + warpN + (ni << 3) + (tig << 1);
            float bz0 = a.bias[c], bz1 = a.bias[c + 1];
            float* p0 = a.C + (size_t)r0 * a.N + c;
            float* p1 = a.C + (size_t)(r0 + 8) * a.N + c;
            p0[0] = acc[mi][ni][0] + bz0;
            p0[1] = acc[mi][ni][1] + bz1;
            p1[0] = acc[mi][ni][2] + bz0;
            p1[1] = acc[mi][ni][3] + bz1;
        }
    }
}

// ---------------- persistent bi-LSTM scan (tensor cores) ----------------------
// 256 blocks = 2 dirs x (4 m-tiles x 32 n-tiles); tile [64 batch x (16h x 4g)].
__global__ void __launch_bounds__(256, 2) k_enc(
    const float* Pf, const float* Pb, const float* Whf, const float* Whb,
    float* oF, float* oB, int ostr, int offF, int offB,
    float* cF, float* cB, const float* zero)
{
    __shared__ SmemU sm;
    int bid = blockIdx.x;
    int dir = bid >> 7, tt = bid & 127;
    int bm = (tt >> 5) << 6, h0 = (tt & 31) << 4;
    const float* W = dir ? Whb : Whf;
    const float* P = dir ? Pb : Pf;
    float* outp = dir ? oB : oF;
    int off = dir ? offB : offF;
    int tid = threadIdx.x;
    int w = tid >> 5, lane = tid & 31, g = lane >> 2, tig = lane & 3;
    int wm = w >> 1, wn = w & 1;
    int tx = tid & 15, ty = tid >> 4;
    int hh = h0 + tx;
    float creg[4] = {0.f, 0.f, 0.f, 0.f};

    for (int t = 0; t < S_; t++) {
        int ti = dir ? (S_ - 1 - t) : t;
        const float* Abase;
        int astr;
        if (t == 0) { Abase = zero + (size_t)bm * H_; astr = H_; }
        else {
            int tp = dir ? (ti + 1) : (ti - 1);
            Abase = outp + (size_t)tp * B_ * ostr + off + (size_t)bm * ostr;
            astr = ostr;
        }
        float acc[4][4];
#pragma unroll
        for (int ni = 0; ni < 4; ni++)
#pragma unroll
            for (int q = 0; q < 4; q++) acc[ni][q] = 0.f;

        mma_tile<true>(acc, sm, Abase, astr, W, h0, wm, wn, g, tig, tid);
        acc_to_Gs(acc, sm, wm, wn, g, tig);
        __syncthreads();

#pragma unroll
        for (int i = 0; i < 4; i++) {
            int b = bm + (ty << 2) + i;
            float4 gq = *(const float4*)&sm.u.Gs[(ty << 2) + i][tx << 2];
            const float* Pr = P + ((size_t)ti * B_ + b) * G_;
            float gi = gq.x + Pr[hh];
            float gf = gq.y + Pr[H_ + hh];
            float gg = gq.z + Pr[2 * H_ + hh];
            float go = gq.w + Pr[3 * H_ + hh];
            float cn = sigu(gf) * creg[i] + sigu(gi) * tanhu(gg);
            creg[i] = cn;
            outp[(size_t)ti * B_ * ostr + (size_t)b * ostr + off + hh] = sigu(go) * tanhu(cn);
        }
        gbar(t + 1, S_);
    }
    float* cd = dir ? cB : cF;
#pragma unroll
    for (int i = 0; i < 4; i++) cd[(size_t)(bm + (ty << 2) + i) * H_ + hh] = creg[i];
}

// ---------------- persistent decoder -----------------------------------------
__device__ __forceinline__ void attn_batch(
    int b, int tout, const float* de, const float* encE, const float* v,
    float* atts, float* sv, float* sde, float* en, float* red)
{
    int tid = threadIdx.x;
    for (int i = tid; i < H_; i += 256) {
        sv[i] = v[i];
        sde[i] = __ldcg(de + (size_t)b * H_ + i);
    }
    __syncthreads();
    int warp = tid >> 5, lane = tid & 31;
    for (int s = warp; s < S_; s += 8) {
        const float* row = encE + ((size_t)b * S_ + s) * H_;
        float acc = 0.f;
        for (int h = lane; h < H_; h += 32)
            acc += tanhu(__ldg(row + h) + sde[h]) * sv[h];
#pragma unroll
        for (int o = 16; o > 0; o >>= 1) acc += __shfl_xor_sync(0xffffffffu, acc, o);
        if (lane == 0) en[s] = acc;
    }
    __syncthreads();
    if (tid < 128) red[tid] = en[tid];
    __syncthreads();
    for (int st = 64; st > 0; st >>= 1) {
        if (tid < st) red[tid] = fmaxf(red[tid], red[tid + st]);
        __syncthreads();
    }
    float mx = red[0];
    __syncthreads();
    float ex = 0.f;
    if (tid < 128) { ex = __expf(en[tid] - mx); red[tid] = ex; }
    __syncthreads();
    for (int st = 64; st > 0; st >>= 1) {
        if (tid < st) red[tid] += red[tid + st];
        __syncthreads();
    }
    float inv = __fdividef(1.f, red[0]);
    if (tid < 128) atts[((size_t)tout * B_ + b) * S_ + tid] = ex * inv;
    __syncthreads();
}

// de tile for blocks idx=0..31: de[64x64] = h1[64xH] @ w2[64xH]^T + b2
__device__ __forceinline__ void de_tile(
    int idx, const float* h1src, const float* w2, const float* b2, float* de,
    SmemU& sm, int wm, int wn, int g, int tig, int tid)
{
    int bm = (idx >> 3) << 6, bn = (idx & 7) << 6;
    float acc[4][4];
#pragma unroll
    for (int ni = 0; ni < 4; ni++)
#pragma unroll
        for (int q = 0; q < 4; q++) acc[ni][q] = 0.f;
    mma_tile<false>(acc, sm, h1src + (size_t)bm * H_, H_, w2 + (size_t)bn * H_, 0,
                    wm, wn, g, tig, tid);
    int r0 = bm + (wm << 4) + g;
#pragma unroll
    for (int ni = 0; ni < 4; ni++) {
        int c = bn + (wn << 5) + (ni << 3) + (tig << 1);
        float bz0 = b2[c], bz1 = b2[c + 1];
        de[(size_t)r0 * H_ + c]           = acc[ni][0] + bz0;
        de[(size_t)r0 * H_ + c + 1]       = acc[ni][1] + bz1;
        de[(size_t)(r0 + 8) * H_ + c]     = acc[ni][2] + bz0;
        de[(size_t)(r0 + 8) * H_ + c + 1] = acc[ni][3] + bz1;
    }
}

__global__ void __launch_bounds__(256, 2) k_dec(
    const float* d0Wh, const float* d1Wi, const float* d1Wh,
    const float* w2, const float* b2, const float* Pd0, const float* d1b,
    float* h0p, float* h1p, const float* c0i, const float* c1i,
    const float* encE, const float* v, float* de, float* atts)
{
    const int KD = 2 * S_ + 2;
    __shared__ SmemU sm;
    int bid = blockIdx.x, tid = threadIdx.x;
    int w = tid >> 5, lane = tid & 31, g = lane >> 2, tig = lane & 3;
    int wm = w >> 1, wn = w & 1;
    int tx = tid & 15, ty = tid >> 4;

    // cell0/cell1 tiles (blocks 0-127): [64b x (16h x 4g)]
    int bmc = ((bid & 127) >> 5) << 6, h0c = (bid & 31) << 4;
    int hhc = h0c + tx;
    float c0reg[4], c1reg[4];
    if (bid < 128) {
#pragma unroll
        for (int i = 0; i < 4; i++) {
            c0reg[i] = c0i[(size_t)(bmc + (ty << 2) + i) * H_ + hhc];
            c1reg[i] = c1i[(size_t)(bmc + (ty << 2) + i) * H_ + hhc];
        }
    }

    int bars = 0;
    for (int t = 0; t < S_; t++) {
        const float* h0r = h0p + (size_t)(t & 1) * BH_;
        float* h0w = h0p + (size_t)((t & 1) ^ 1) * BH_;
        const float* h1r = h1p + (size_t)(t & 1) * BH_;
        float* h1w = h1p + (size_t)((t & 1) ^ 1) * BH_;

        // ---- ph1: cell0(t) [0-127] || de(t-1) [128-159] (h1r = h1 after t-1)
        if (bid < 128) {
            float acc[4][4];
#pragma unroll
            for (int ni = 0; ni < 4; ni++)
#pragma unroll
                for (int q = 0; q < 4; q++) acc[ni][q] = 0.f;
            mma_tile<true>(acc, sm, h0r + (size_t)bmc * H_, H_, d0Wh, h0c, wm, wn, g, tig, tid);
            acc_to_Gs(acc, sm, wm, wn, g, tig);
            __syncthreads();
            float pi = Pd0[hhc], pf = Pd0[H_ + hhc], pg = Pd0[2 * H_ + hhc], po = Pd0[3 * H_ + hhc];
#pragma unroll
            for (int i = 0; i < 4; i++) {
                int b = bmc + (ty << 2) + i;
                float4 gq = *(const float4*)&sm.u.Gs[(ty << 2) + i][tx << 2];
                float cn = sigu(gq.y + pf) * c0reg[i] + sigu(gq.x + pi) * tanhu(gq.z + pg);
                c0reg[i] = cn;
                h0w[(size_t)b * H_ + hhc] = sigu(gq.w + po) * tanhu(cn);
            }
        } else if (bid < 160 && t > 0) {
            de_tile(bid - 128, h1r, w2, b2, de, sm, wm, wn, g, tig, tid);
        }
        gbar(++bars, KD);

        // ---- ph2: cell1(t) [0-127] || attention(t-1) both batches [128-255]
        if (bid < 128) {
            float acc[4][4];
#pragma unroll
            for (int ni = 0; ni < 4; ni++)
#pragma unroll
                for (int q = 0; q < 4; q++) acc[ni][q] = 0.f;
            mma_tile<true>(acc, sm, h0w + (size_t)bmc * H_, H_, d1Wi, h0c, wm, wn, g, tig, tid);
            mma_tile<true>(acc, sm, h1r + (size_t)bmc * H_, H_, d1Wh, h0c, wm, wn, g, tig, tid);
            acc_to_Gs(acc, sm, wm, wn, g, tig);
            __syncthreads();
            float pi = d1b[hhc], pf = d1b[H_ + hhc], pg = d1b[2 * H_ + hhc], po = d1b[3 * H_ + hhc];
#pragma unroll
            for (int i = 0; i < 4; i++) {
                int b = bmc + (ty << 2) + i;
                float4 gq = *(const float4*)&sm.u.Gs[(ty << 2) + i][tx << 2];
                float cn = sigu(gq.y + pf) * c1reg[i] + sigu(gq.x + pi) * tanhu(gq.z + pg);
                c1reg[i] = cn;
                h1w[(size_t)b * H_ + hhc] = sigu(gq.w + po) * tanhu(cn);
            }
        } else if (t > 0) {
            attn_batch((bid - 128) * 2, t - 1, de, encE, v, atts,
                       sm.u.at.sv, sm.u.at.sde, sm.u.at.en, sm.u.at.red);
            attn_batch((bid - 128) * 2 + 1, t - 1, de, encE, v, atts,
                       sm.u.at.sv, sm.u.at.sde, sm.u.at.en, sm.u.at.red);
        }
        gbar(++bars, KD);
    }

    // ---- tail: de(S-1) then attention(S-1)
    const float* h1fin = h1p + (size_t)(((S_ - 1) & 1) ^ 1) * BH_;
    if (bid >= 128 && bid < 160) {
        de_tile(bid - 128, h1fin, w2, b2, de, sm, wm, wn, g, tig, tid);
    }
    gbar(++bars, KD);
    attn_batch(bid, S_ - 1, de, encE, v, atts,
               sm.u.at.sv, sm.u.at.sde, sm.u.at.en, sm.u.at.red);
    gbar(++bars, KD);   // bars == KD: resets phase+flags to 0
}

// ---------------- host driver ------------------------------------------------
extern "C" void kernel_launch(void* const* d_in, const int* in_sizes, int n_in,
                              void* d_out, int out_size) {
    const int*   inputs = (const int*)d_in[0];
    const float* emb    = (const float*)d_in[1];
    const float* e0f_Wi = (const float*)d_in[2];
    const float* e0f_Wh = (const float*)d_in[3];
    const float* e0f_b  = (const float*)d_in[4];
    const float* e0b_Wi = (const float*)d_in[5];
    const float* e0b_Wh = (const float*)d_in[6];
    const float* e0b_b  = (const float*)d_in[7];
    const float* e1f_Wi = (const float*)d_in[8];
    const float* e1f_Wh = (const float*)d_in[9];
    const float* e1f_b  = (const float*)d_in[10];
    const float* e1b_Wi = (const float*)d_in[11];
    const float* e1b_Wh = (const float*)d_in[12];
    const float* e1b_b  = (const float*)d_in[13];
    const float* d0_Wi  = (const float*)d_in[14];
    const float* d0_Wh  = (const float*)d_in[15];
    const float* d0_b   = (const float*)d_in[16];
    const float* d1_Wi  = (const float*)d_in[17];
    const float* d1_Wh  = (const float*)d_in[18];
    const float* d1_b   = (const float*)d_in[19];
    const float* w1     = (const float*)d_in[20];
    const float* b1     = (const float*)d_in[21];
    const float* w2     = (const float*)d_in[22];
    const float* b2     = (const float*)d_in[23];
    const float* v      = (const float*)d_in[24];
    float* out = (float*)d_out;

    float *x, *Pf, *Pb, *x1, *of1, *ob1, *enc, *encE;
    float *cf0, *cb0, *cf1, *cb1, *zero, *h0, *h1, *c0, *c1, *de, *Pd0, *atts;
    cudaGetSymbolAddress((void**)&x, g_x);
    cudaGetSymbolAddress((void**)&Pf, g_Pf);
    cudaGetSymbolAddress((void**)&Pb, g_Pb);
    cudaGetSymbolAddress((void**)&x1, g_x1);
    cudaGetSymbolAddress((void**)&of1, g_of1);
    cudaGetSymbolAddress((void**)&ob1, g_ob1);
    cudaGetSymbolAddress((void**)&enc, g_enc);
    cudaGetSymbolAddress((void**)&encE, g_encE);
    cudaGetSymbolAddress((void**)&cf0, g_cf0);
    cudaGetSymbolAddress((void**)&cb0, g_cb0);
    cudaGetSymbolAddress((void**)&cf1, g_cf1);
    cudaGetSymbolAddress((void**)&cb1, g_cb1);
    cudaGetSymbolAddress((void**)&zero, g_zero);
    cudaGetSymbolAddress((void**)&h0, g_h0);
    cudaGetSymbolAddress((void**)&h1, g_h1);
    cudaGetSymbolAddress((void**)&c0, g_c0);
    cudaGetSymbolAddress((void**)&c1, g_c1);
    cudaGetSymbolAddress((void**)&de, g_de);
    cudaGetSymbolAddress((void**)&Pd0, g_Pd0);
    cudaGetSymbolAddress((void**)&atts, g_atts);

    // 1) embedding
    k_embed<<<SB_ * E_ / 256, 256>>>(inputs, emb, x);

    // 2) layer0 input projections + scan (h written into x1 halves)
    {
        GArg f{x, e0f_Wi, Pf, e0f_b, G_};
        GArg b{x, e0b_Wi, Pb, e0b_b, G_};
        k_gemm<<<dim3(G_ / 64, SB_ / 128, 2), 256>>>(f, b, E_);
    }
    k_enc<<<NB_, 256>>>(Pf, Pb, e0f_Wh, e0b_Wh, x1, x1, 2 * H_, 0, H_, cf0, cb0, zero);

    // 3) layer1 input projections + scan
    {
        GArg f{x1, e1f_Wi, Pf, e1f_b, G_};
        GArg b{x1, e1b_Wi, Pb, e1b_b, G_};
        k_gemm<<<dim3(G_ / 64, SB_ / 128, 2), 256>>>(f, b, 2 * H_);
    }
    k_enc<<<NB_, 256>>>(Pf, Pb, e1f_Wh, e1b_Wh, of1, ob1, H_, 0, 0, cf1, cb1, zero);

    // 4) encoder out + hoisted attention energy
    k_encout<<<SB_ * H_ / 256, 256>>>(of1, ob1, enc);
    {
        GArg a{enc, w1, encE, b1, H_};
        k_gemm<<<dim3(H_ / 64, SB_ / 128, 1), 256>>>(a, a, H_);
    }

    // 5) decoder init + constant input projection
    k_decinit<<<BH_ / 256, 256>>>(x1, of1, ob1, cf0, cb0, cf1, cb1, h0, c0, h1, c1);
    k_vecproj<<<G_ / 256, 256>>>(emb, d0_Wi, d0_b, Pd0);

    // 6) decoder (persistent, 2 barriers/step)
    k_dec<<<NB_, 256>>>(d0_Wh, d1_Wi, d1_Wh, w2, b2, Pd0, d1_b,
                        h0, h1, c0, c1, encE, v, de, atts);

    // 7) transpose atts[t][b][s] -> out[b][s][t]
    k_trans<<<dim3(S_ / 32, S_ / 32, B_), 256>>>(atts, out);
}